// round 14
// baseline (speedup 1.0000x reference)
#include <cuda_runtime.h>
#include <stdint.h>

// QuantizationLayer: out[i, 4j + k] = bit (3-k) of rint(x[i,j]*16 - 0.5), as f32.
// Last unmeasured cell of the design matrix: __ldcg loads (L2-resident across
// graph replays, skip per-launch-flushed L1) + UNROLL=8 (MLP=8, half the
// per-element loop overhead of the champion). Store path identical to champion:
// block-strided lane-dense 128-bit .cs stores.

#define TPB 256
#define UNROLL 8

__global__ void __launch_bounds__(TPB, 4)
quant_bits_kernel(const float* __restrict__ x, float* __restrict__ out, int n)
{
    int base = blockIdx.x * (TPB * UNROLL) + threadIdx.x;
    float4* out4 = reinterpret_cast<float4*>(out);

    if (base + (UNROLL - 1) * TPB < n) {
        // Full tile: 8 front-batched independent L2-cached loads.
        float v[UNROLL];
#pragma unroll
        for (int u = 0; u < UNROLL; u++)
            v[u] = __ldcg(&x[base + u * TPB]);

#pragma unroll
        for (int u = 0; u < UNROLL; u++) {
            int i = base + u * TPB;

            // Match JAX exactly: two separate f32 ops, round-half-even.
            float t = v[u] * 16.0f;
            t = t - 0.5f;
            int num = (int)rintf(t);
            num &= 255;  // uint8 wraparound emulation (no-op for x in [0,1))

            float4 bits;
            bits.x = (num & 8) ? 1.0f : 0.0f;
            bits.y = (num & 4) ? 1.0f : 0.0f;
            bits.z = (num & 2) ? 1.0f : 0.0f;
            bits.w = (num & 1) ? 1.0f : 0.0f;
            __stcs(out4 + i, bits);
        }
    } else {
        // Tail block (n not divisible by TPB*UNROLL).
#pragma unroll
        for (int u = 0; u < UNROLL; u++) {
            int i = base + u * TPB;
            if (i >= n) continue;

            float t = __ldcg(&x[i]) * 16.0f;
            t = t - 0.5f;
            int num = (int)rintf(t);
            num &= 255;

            float4 bits;
            bits.x = (num & 8) ? 1.0f : 0.0f;
            bits.y = (num & 4) ? 1.0f : 0.0f;
            bits.z = (num & 2) ? 1.0f : 0.0f;
            bits.w = (num & 1) ? 1.0f : 0.0f;
            __stcs(out4 + i, bits);
        }
    }
}

extern "C" void kernel_launch(void* const* d_in, const int* in_sizes, int n_in,
                              void* d_out, int out_size)
{
    const float* x = (const float*)d_in[0];
    float* out = (float*)d_out;
    int n = in_sizes[0];   // 4096 * 2048 = 8388608

    int blocks = (n + TPB * UNROLL - 1) / (TPB * UNROLL);
    quant_bits_kernel<<<blocks, TPB>>>(x, out, n);
}

// round 15
// speedup vs baseline: 1.0012x; 1.0012x over previous
#include <cuda_runtime.h>
#include <stdint.h>

// QuantizationLayer: out[i, 4j + k] = bit (3-k) of rint(x[i,j]*16 - 0.5), as f32.
// Champion recipe (R11: __ldcg loads L2-resident across replays, block-strided
// lane-dense 128-bit .cs stores, 4 elements/thread, one-shot exact grid) with
// the one never-varied knob: TPB 256 -> 512 (warp packing / CTA count probe).

#define TPB 512
#define UNROLL 4

__global__ void __launch_bounds__(TPB, 4)
quant_bits_kernel(const float* __restrict__ x, float* __restrict__ out, int n)
{
    int base = blockIdx.x * (TPB * UNROLL) + threadIdx.x;
    float4* out4 = reinterpret_cast<float4*>(out);

    // Front-batched independent L2-cached loads (skip L1; L2-resident across replays).
    float v[UNROLL];
#pragma unroll
    for (int u = 0; u < UNROLL; u++) {
        int i = base + u * TPB;
        v[u] = (i < n) ? __ldcg(&x[i]) : 0.0f;
    }

#pragma unroll
    for (int u = 0; u < UNROLL; u++) {
        int i = base + u * TPB;
        if (i >= n) continue;

        // Match JAX exactly: two separate f32 ops, round-half-even.
        float t = v[u] * 16.0f;
        t = t - 0.5f;
        int num = (int)rintf(t);
        num &= 255;  // uint8 wraparound emulation (no-op for x in [0,1))

        float4 bits;
        bits.x = (num & 8) ? 1.0f : 0.0f;
        bits.y = (num & 4) ? 1.0f : 0.0f;
        bits.z = (num & 2) ? 1.0f : 0.0f;
        bits.w = (num & 1) ? 1.0f : 0.0f;
        __stcs(out4 + i, bits);   // evict-first: don't displace L2-resident input
    }
}

extern "C" void kernel_launch(void* const* d_in, const int* in_sizes, int n_in,
                              void* d_out, int out_size)
{
    const float* x = (const float*)d_in[0];
    float* out = (float*)d_out;
    int n = in_sizes[0];   // 4096 * 2048 = 8388608

    int blocks = (n + TPB * UNROLL - 1) / (TPB * UNROLL);
    quant_bits_kernel<<<blocks, TPB>>>(x, out, n);
}

// round 16
// speedup vs baseline: 1.0072x; 1.0060x over previous
#include <cuda_runtime.h>
#include <stdint.h>

// QuantizationLayer: out[i, 4j + k] = bit (3-k) of rint(x[i,j]*16 - 0.5), as f32.
// Champion recipe (R11): __ldcg loads (skip per-launch-flushed L1, L2-resident
// across graph replays), block-strided lane-dense 128-bit .cs stores,
// 4 elements/thread, one-shot exact grid. Final block-size probe: TPB=128
// (block-size trend measured 512 < 256; finest CTA granularity balances the
// asymmetric L2-die drain and eliminates wave-tail quantization).

#define TPB 128
#define UNROLL 4

__global__ void __launch_bounds__(TPB, 16)
quant_bits_kernel(const float* __restrict__ x, float* __restrict__ out, int n)
{
    int base = blockIdx.x * (TPB * UNROLL) + threadIdx.x;
    float4* out4 = reinterpret_cast<float4*>(out);

    // Front-batched independent L2-cached loads (MLP=4).
    float v[UNROLL];
#pragma unroll
    for (int u = 0; u < UNROLL; u++) {
        int i = base + u * TPB;
        v[u] = (i < n) ? __ldcg(&x[i]) : 0.0f;
    }

#pragma unroll
    for (int u = 0; u < UNROLL; u++) {
        int i = base + u * TPB;
        if (i >= n) continue;

        // Match JAX exactly: two separate f32 ops, round-half-even.
        float t = v[u] * 16.0f;
        t = t - 0.5f;
        int num = (int)rintf(t);
        num &= 255;  // uint8 wraparound emulation (no-op for x in [0,1))

        float4 bits;
        bits.x = (num & 8) ? 1.0f : 0.0f;
        bits.y = (num & 4) ? 1.0f : 0.0f;
        bits.z = (num & 2) ? 1.0f : 0.0f;
        bits.w = (num & 1) ? 1.0f : 0.0f;
        __stcs(out4 + i, bits);   // evict-first: don't displace L2-resident input
    }
}

extern "C" void kernel_launch(void* const* d_in, const int* in_sizes, int n_in,
                              void* d_out, int out_size)
{
    const float* x = (const float*)d_in[0];
    float* out = (float*)d_out;
    int n = in_sizes[0];   // 4096 * 2048 = 8388608

    int blocks = (n + TPB * UNROLL - 1) / (TPB * UNROLL);
    quant_bits_kernel<<<blocks, TPB>>>(x, out, n);
}

// round 17
// speedup vs baseline: 1.0663x; 1.0587x over previous
#include <cuda_runtime.h>
#include <stdint.h>

// QuantizationLayer: out[i, 4j + k] = bit (3-k) of rint(x[i,j]*16 - 0.5), as f32.
// Champion recipe (__ldcg loads L2-resident across replays, 128-bit .cs stores,
// UNROLL=4, TPB=256, one-shot grid) with WARP-TILED indexing: each warp owns a
// contiguous span (4x512B store bursts forming one 2KB contiguous write, 4x128B
// loads forming one 512B contiguous read) instead of 4 bursts scattered 4KB
// apart. Per-instruction lane density unchanged; targets DRAM/LTS burst locality
// on the drain-bound write stream.

#define TPB 256
#define UNROLL 4

__global__ void __launch_bounds__(TPB, 8)
quant_bits_kernel(const float* __restrict__ x, float* __restrict__ out, int n)
{
    int warp_id = (blockIdx.x * TPB + threadIdx.x) >> 5;   // global warp index
    int lane    = threadIdx.x & 31;
    int base    = warp_id * (32 * UNROLL) + lane;          // warp-contiguous tile
    float4* out4 = reinterpret_cast<float4*>(out);

    // Front-batched independent L2-cached loads (skip L1; L2-resident across replays).
    float v[UNROLL];
#pragma unroll
    for (int u = 0; u < UNROLL; u++) {
        int i = base + u * 32;
        v[u] = (i < n) ? __ldcg(&x[i]) : 0.0f;
    }

#pragma unroll
    for (int u = 0; u < UNROLL; u++) {
        int i = base + u * 32;
        if (i >= n) continue;

        // Match JAX exactly: two separate f32 ops, round-half-even.
        float t = v[u] * 16.0f;
        t = t - 0.5f;
        int num = (int)rintf(t);
        num &= 255;  // uint8 wraparound emulation (no-op for x in [0,1))

        float4 bits;
        bits.x = (num & 8) ? 1.0f : 0.0f;
        bits.y = (num & 4) ? 1.0f : 0.0f;
        bits.z = (num & 2) ? 1.0f : 0.0f;
        bits.w = (num & 1) ? 1.0f : 0.0f;
        __stcs(out4 + i, bits);   // evict-first: don't displace L2-resident input
    }
}

extern "C" void kernel_launch(void* const* d_in, const int* in_sizes, int n_in,
                              void* d_out, int out_size)
{
    const float* x = (const float*)d_in[0];
    float* out = (float*)d_out;
    int n = in_sizes[0];   // 4096 * 2048 = 8388608

    int blocks = (n + TPB * UNROLL - 1) / (TPB * UNROLL);
    quant_bits_kernel<<<blocks, TPB>>>(x, out, n);
}